// round 9
// baseline (speedup 1.0000x reference)
#include <cuda_runtime.h>

// KernelNorm2d: kernel=2x2, stride=2, pad=0 -> identity spatial mapping.
// out[b,c,h,w] = (x[b,c,h,w] - mu[b,h/2,w/2]) * rsqrt(var[b,h/2,w/2] + eps)
// group = 64 channels x 2x2 pixels = 256 values per window.
//
// Persistent software-pipelined design. 456 CTAs (152 SMs x 3), 256 threads.
// Tile = (batch, row-pair, column-block of 16 float4) as in R6:
//   thread t owns float4-col (t&15), segments seg = (t>>4) + 16*it, it=0..7
//   -> warp accesses are 4 fully-dense 128B lines per LDG/STG.128.
// Pipeline: loads for tile t+1 issue BEFORE reduce/store of tile t, keeping
// 8 LDG.128 in flight per thread continuously (kills load-phase gaps from
// CTA phase-locking). Double-buffered smem partial exchange -> one barrier
// per tile is race-free. __ldcs/__stcs: pure streaming, no reuse.

#define EPSV  1e-5f
#define NTILE 8192
#define GRID  456

__global__ __launch_bounds__(256, 3)
void knorm2d_kernel(const float* __restrict__ x, float* __restrict__ y) {
    const int t    = threadIdx.x;
    const int jloc = t & 15;     // float4-col within block
    const int s0   = t >> 4;     // starting segment 0..15

    const float4* __restrict__ xb = reinterpret_cast<const float4*>(x);
    float4* __restrict__ yb = reinterpret_cast<float4*>(y);

    __shared__ float4 red[2][256];

    // Per-thread constant part of the address (segment s0 folded in):
    // idx(tile, it) = tbase(tile) + it*131072
    const int thrOff = ((s0 >> 1) * 16384) + ((s0 & 1) * 64) + jloc;

    // tile -> base index: tile = (b*128 + i)*4 + cblk
    auto tileBase = [&](int tile) {
        const int cblk = tile & 3;
        const int i    = (tile >> 2) & 127;
        const int b    = tile >> 9;
        return (b * 16384 + 2 * i) * 64 + (cblk << 4) + thrOff;
    };

    int tile = blockIdx.x;
    int tb   = tileBase(tile);

    float4 v[8];
#pragma unroll
    for (int it = 0; it < 8; ++it) v[it] = __ldcs(xb + tb + it * 131072);

    int p = 0;
    while (true) {
        const int  ntile = tile + GRID;
        const bool more  = ntile < NTILE;
        int ntb = 0;
        float4 w[8];
        if (more) {
            ntb = tileBase(ntile);
#pragma unroll
            for (int it = 0; it < 8; ++it) w[it] = __ldcs(xb + ntb + it * 131072);
        }

        // Partial sums for this thread's two windows (A = x,y; B = z,w)
        float sA = 0.f, ssA = 0.f, sB = 0.f, ssB = 0.f;
#pragma unroll
        for (int k = 0; k < 8; ++k) {
            const float4 q = v[k];
            sA += q.x + q.y;
            ssA = fmaf(q.x, q.x, fmaf(q.y, q.y, ssA));
            sB += q.z + q.w;
            ssB = fmaf(q.z, q.z, fmaf(q.w, q.w, ssB));
        }

        red[p][t] = make_float4(sA, ssA, sB, ssB);
        __syncthreads();

        float SA = 0.f, SSA = 0.f, SB = 0.f, SSB = 0.f;
#pragma unroll
        for (int k = 0; k < 16; ++k) {
            const float4 q = red[p][(k << 4) | jloc];
            SA += q.x; SSA += q.y; SB += q.z; SSB += q.w;
        }

        const float inv  = 1.0f / 256.0f;
        const float muA  = SA * inv;
        const float muB  = SB * inv;
        const float varA = fmaf(-muA, muA, SSA * inv);
        const float varB = fmaf(-muB, muB, SSB * inv);
        const float rA   = rsqrtf(varA + EPSV);
        const float rB   = rsqrtf(varB + EPSV);

#pragma unroll
        for (int it = 0; it < 8; ++it) {
            float4 q = v[it];
            q.x = (q.x - muA) * rA;
            q.y = (q.y - muA) * rA;
            q.z = (q.z - muB) * rB;
            q.w = (q.w - muB) * rB;
            __stcs(yb + tb + it * 131072, q);
        }

        if (!more) break;
#pragma unroll
        for (int it = 0; it < 8; ++it) v[it] = w[it];
        tb   = ntb;
        tile = ntile;
        p ^= 1;
    }
}

extern "C" void kernel_launch(void* const* d_in, const int* in_sizes, int n_in,
                              void* d_out, int out_size) {
    const float* x = (const float*)d_in[0];
    float* y = (float*)d_out;
    knorm2d_kernel<<<GRID, 256>>>(x, y);
}

// round 10
// speedup vs baseline: 1.1335x; 1.1335x over previous
#include <cuda_runtime.h>

// KernelNorm2d: kernel=2x2, stride=2, pad=0 -> identity spatial mapping.
// out[b,c,h,w] = (x[b,c,h,w] - mu[b,h/2,w/2]) * rsqrt(var[b,h/2,w/2] + eps)
// group = 64 channels x 2x2 pixels = 256 values per window.
//
// Flat-grid dense-access design (best measured: ncu 78.0us, ~6.2TB/s, which
// matches the HBM mixed read/write ceiling). CTA = (batch, column-block,
// row-pair); row-pair fastest in bid so concurrent CTAs stream adjacent
// rows (DRAM page locality). Thread t owns float4-col (t&15), segments
// seg = (t>>4) + 16*it (c = seg>>1, r = seg&1): each warp LDG/STG.128
// covers 4 fully-dense 128B lines. Thread's 8 float4 belong to exactly
// 2 windows (A = x,y lanes; B = z,w lanes); one 4KB smem exchange + one
// barrier finalizes stats; normalize from registers. __ldcs/__stcs:
// pure streaming, zero reuse.

#define EPSV 1e-5f

__global__ __launch_bounds__(256, 4)
void knorm2d_kernel(const float* __restrict__ x, float* __restrict__ y) {
    const int bid  = blockIdx.x;
    const int i    = bid & 127;        // row-pair (fastest varying)
    const int cblk = (bid >> 7) & 3;   // column block (16 float4-cols)
    const int b    = bid >> 9;         // batch
    const int t    = threadIdx.x;
    const int jloc = t & 15;           // float4-col within block
    const int s0   = t >> 4;           // starting segment 0..15

    const float4* __restrict__ xb = reinterpret_cast<const float4*>(x);
    float4* __restrict__ yb = reinterpret_cast<float4*>(y);

    const int j4 = (cblk << 4) | jloc;   // global float4-col 0..63
    // float4 index: ((b*64 + c)*256 + 2i + r)*64 + j4 = base0 + c*16384 + r*64
    const int chanStride4 = 256 * 64;    // 16384
    const int base0 = (b * 64 * 256 + 2 * i) * 64 + j4;

    float4 v[8];
    int segIdx[8];
#pragma unroll
    for (int it = 0; it < 8; ++it) {
        const int seg = s0 + (it << 4);                 // 0..127
        const int idx = base0 + (seg >> 1) * chanStride4 + (seg & 1) * 64;
        segIdx[it] = idx;
        v[it] = __ldcs(xb + idx);
    }

    // Partial sums for this thread's two windows
    float sA = 0.f, ssA = 0.f, sB = 0.f, ssB = 0.f;
#pragma unroll
    for (int k = 0; k < 8; ++k) {
        const float4 q = v[k];
        sA += q.x + q.y;
        ssA = fmaf(q.x, q.x, fmaf(q.y, q.y, ssA));
        sB += q.z + q.w;
        ssB = fmaf(q.z, q.z, fmaf(q.w, q.w, ssB));
    }

    // Exchange partials: the 16 threads with equal jloc share each window pair.
    __shared__ float4 red[256];
    red[t] = make_float4(sA, ssA, sB, ssB);
    __syncthreads();

    float SA = 0.f, SSA = 0.f, SB = 0.f, SSB = 0.f;
#pragma unroll
    for (int k = 0; k < 16; ++k) {
        const float4 q = red[(k << 4) | jloc];
        SA += q.x; SSA += q.y; SB += q.z; SSB += q.w;
    }

    const float inv  = 1.0f / 256.0f;
    const float muA  = SA * inv;
    const float muB  = SB * inv;
    const float varA = fmaf(-muA, muA, SSA * inv);
    const float varB = fmaf(-muB, muB, SSB * inv);
    const float rA   = rsqrtf(varA + EPSV);
    const float rB   = rsqrtf(varB + EPSV);

#pragma unroll
    for (int it = 0; it < 8; ++it) {
        float4 q = v[it];
        q.x = (q.x - muA) * rA;
        q.y = (q.y - muA) * rA;
        q.z = (q.z - muB) * rB;
        q.w = (q.w - muB) * rB;
        __stcs(yb + segIdx[it], q);
    }
}

extern "C" void kernel_launch(void* const* d_in, const int* in_sizes, int n_in,
                              void* d_out, int out_size) {
    const float* x = (const float*)d_in[0];
    float* y = (float*)d_out;
    knorm2d_kernel<<<16 * 128 * 4, 256>>>(x, y);
}